// round 15
// baseline (speedup 1.0000x reference)
#include <cuda_runtime.h>
#include <cuda_bf16.h>
#include <math.h>
#include <cstdint>

// Problem constants
#define BB   2
#define SS   768
#define CA   768
#define CS   384
#define CZ   128
#define HH   16
#define HD   48
#define MM   (BB*SS)          // 1536
#define EPS  1e-5f
#define SCALE (0.14433756729740643f)  // 1/sqrt(48)

// ---------------- scratch (device globals) ----------------------------------
__device__ float g_sn   [MM*CS];
__device__ float g_lna  [MM*CA];
__device__ float g_an   [MM*CA];
__device__ float g_q    [BB*HH*SS*HD];      // [b,h,s,d]
__device__ float g_k    [BB*HH*SS*HD];      // [b,h,s,d]
__device__ float g_v    [BB*HH*SS*HD];      // [b,h,s,d]
__device__ float g_gate [MM*CA];
__device__ float g_bias [BB*HH*SS*SS];      // pair bias, layout [b,h,j,i] (i contiguous)
__device__ float g_go   [MM*CA];

// ---------------- helpers ----------------------------------------------------
__device__ __forceinline__ float sigmoidf_(float x) { return 1.0f / (1.0f + expf(-x)); }

__device__ __forceinline__ uint32_t f2tf32(float f) {
    uint32_t r;
    asm("cvt.rna.tf32.f32 %0, %1;" : "=r"(r) : "f"(f));
    return r;
}
__device__ __forceinline__ uint32_t pack_bf16x2(float lo, float hi) {
    uint32_t r;
    asm("cvt.rn.bf16x2.f32 %0, %1, %2;" : "=r"(r) : "f"(hi), "f"(lo));
    return r;
}
__device__ __forceinline__ uint32_t smem_u32(const void* p) {
    uint32_t a;
    asm("{ .reg .u64 t; cvta.to.shared.u64 t, %1; cvt.u32.u64 %0, t; }"
        : "=r"(a) : "l"(p));
    return a;
}

#define CP16(dst, src) asm volatile("cp.async.ca.shared.global [%0], [%1], 16;" :: "r"(dst), "l"(src))
#define CP4(dst, src)  asm volatile("cp.async.ca.shared.global [%0], [%1], 4;"  :: "r"(dst), "l"(src))
#define CP_COMMIT()    asm volatile("cp.async.commit_group;" ::: "memory")
#define CP_WAIT1()     asm volatile("cp.async.wait_group 1;" ::: "memory")
#define CP_WAIT0()     asm volatile("cp.async.wait_group 0;" ::: "memory")

__device__ __forceinline__ void mma_tf32(float* d, const uint32_t* a, const uint32_t* b) {
    asm volatile("mma.sync.aligned.m16n8k8.row.col.f32.tf32.tf32.f32 "
        "{%0,%1,%2,%3}, {%4,%5,%6,%7}, {%8,%9}, {%0,%1,%2,%3};"
        : "+f"(d[0]), "+f"(d[1]), "+f"(d[2]), "+f"(d[3])
        : "r"(a[0]), "r"(a[1]), "r"(a[2]), "r"(a[3]), "r"(b[0]), "r"(b[1]));
}
__device__ __forceinline__ void mma_bf16(float* d, const uint32_t* a, const uint32_t* b) {
    asm volatile("mma.sync.aligned.m16n8k16.row.col.f32.bf16.bf16.f32 "
        "{%0,%1,%2,%3}, {%4,%5,%6,%7}, {%8,%9}, {%0,%1,%2,%3};"
        : "+f"(d[0]), "+f"(d[1]), "+f"(d[2]), "+f"(d[3])
        : "r"(a[0]), "r"(a[1]), "r"(a[2]), "r"(a[3]), "r"(b[0]), "r"(b[1]));
}

__device__ float2 blockReduceSum2(float a, float b) {
    __shared__ float sa[32], sb[32];
    int lane = threadIdx.x & 31, wid = threadIdx.x >> 5;
    #pragma unroll
    for (int o = 16; o; o >>= 1) {
        a += __shfl_xor_sync(0xffffffffu, a, o);
        b += __shfl_xor_sync(0xffffffffu, b, o);
    }
    if (lane == 0) { sa[wid] = a; sb[wid] = b; }
    __syncthreads();
    if (wid == 0) {
        int nw = (blockDim.x + 31) >> 5;
        a = (lane < nw) ? sa[lane] : 0.0f;
        b = (lane < nw) ? sb[lane] : 0.0f;
        #pragma unroll
        for (int o = 16; o; o >>= 1) {
            a += __shfl_xor_sync(0xffffffffu, a, o);
            b += __shfl_xor_sync(0xffffffffu, b, o);
        }
        if (lane == 0) { sa[0] = a; sb[0] = b; }
    }
    __syncthreads();
    float2 r = make_float2(sa[0], sb[0]);
    __syncthreads();
    return r;
}

// ---------------- LN kernel --------------------------------------------------
__global__ void ln_kernel(const float* __restrict__ s, const float* __restrict__ a,
                          const float* __restrict__ gamma_s) {
    int r = blockIdx.x;
    int tid = threadIdx.x;
    const float* srow = s + (long)r * CS;
    float sum = 0.f, sq = 0.f;
    for (int c = tid; c < CS; c += blockDim.x) { float v = srow[c]; sum += v; sq += v * v; }
    float2 t = blockReduceSum2(sum, sq);
    float mean = t.x / CS, var = t.y / CS - mean * mean;
    float rstd = rsqrtf(var + EPS);
    for (int c = tid; c < CS; c += blockDim.x)
        g_sn[(long)r * CS + c] = (srow[c] - mean) * rstd * gamma_s[c];

    const float* arow = a + (long)r * CA;
    sum = 0.f; sq = 0.f;
    for (int c = tid; c < CA; c += blockDim.x) { float v = arow[c]; sum += v; sq += v * v; }
    t = blockReduceSum2(sum, sq);
    mean = t.x / CA; var = t.y / CA - mean * mean;
    rstd = rsqrtf(var + EPS);
    for (int c = tid; c < CA; c += blockDim.x)
        g_lna[(long)r * CA + c] = (arow[c] - mean) * rstd;
}

// ---------------- common GEMM machinery (128x64 tile, BK=32, cp.async) ------
#define APITCH 36
#define BPITCH 36
#define A_WORDS (128 * APITCH)               // 4608
#define B_WORDS (64 * BPITCH)                // 2304
#define SPITCH 68
#define STAGE_WORDS (128 * SPITCH)           // 8704

__device__ __forceinline__ void frag_compute_cvt(const float* As, const float* Bs,
        float (&acc)[2][4][4], int wr, int wc, int g4, int q4) {
    #pragma unroll
    for (int kc = 0; kc < 4; kc++) {
        int kb = kc * 8 + q4;
        uint32_t af[2][4];
        #pragma unroll
        for (int mt = 0; mt < 2; mt++) {
            int r = wr + mt * 16 + g4;
            af[mt][0] = f2tf32(As[r * APITCH + kb]);
            af[mt][1] = f2tf32(As[(r + 8) * APITCH + kb]);
            af[mt][2] = f2tf32(As[r * APITCH + kb + 4]);
            af[mt][3] = f2tf32(As[(r + 8) * APITCH + kb + 4]);
        }
        #pragma unroll
        for (int nt = 0; nt < 4; nt++) {
            int c = wc + nt * 8 + g4;
            uint32_t bf[2] = {f2tf32(Bs[c * BPITCH + kb]), f2tf32(Bs[c * BPITCH + kb + 4])};
            #pragma unroll
            for (int mt = 0; mt < 2; mt++)
                mma_tf32(acc[mt][nt], af[mt], bf);
        }
    }
}

__device__ __forceinline__ void frag_compute2_cvt(const float* As, const float* Bs1,
        const float* Bs2, float (&acc1)[2][4][4], float (&acc2)[2][4][4],
        int wr, int wc, int g4, int q4) {
    #pragma unroll
    for (int kc = 0; kc < 4; kc++) {
        int kb = kc * 8 + q4;
        uint32_t af[2][4];
        #pragma unroll
        for (int mt = 0; mt < 2; mt++) {
            int r = wr + mt * 16 + g4;
            af[mt][0] = f2tf32(As[r * APITCH + kb]);
            af[mt][1] = f2tf32(As[(r + 8) * APITCH + kb]);
            af[mt][2] = f2tf32(As[r * APITCH + kb + 4]);
            af[mt][3] = f2tf32(As[(r + 8) * APITCH + kb + 4]);
        }
        #pragma unroll
        for (int nt = 0; nt < 4; nt++) {
            int c = wc + nt * 8 + g4;
            uint32_t b1[2] = {f2tf32(Bs1[c * BPITCH + kb]), f2tf32(Bs1[c * BPITCH + kb + 4])};
            uint32_t b2[2] = {f2tf32(Bs2[c * BPITCH + kb]), f2tf32(Bs2[c * BPITCH + kb + 4])};
            #pragma unroll
            for (int mt = 0; mt < 2; mt++) {
                mma_tf32(acc1[mt][nt], af[mt], b1);
                mma_tf32(acc2[mt][nt], af[mt], b2);
            }
        }
    }
}

__device__ __forceinline__ void stage_acc(float* st, const float (&acc)[2][4][4],
        int wr, int wc, int g4, int q4) {
    #pragma unroll
    for (int mt = 0; mt < 2; mt++) {
        #pragma unroll
        for (int nt = 0; nt < 4; nt++) {
            int rr = wr + mt * 16 + g4;
            int cc = wc + nt * 8 + 2 * q4;
            st[rr * SPITCH + cc]           = acc[mt][nt][0];
            st[rr * SPITCH + cc + 1]       = acc[mt][nt][1];
            st[(rr + 8) * SPITCH + cc]     = acc[mt][nt][2];
            st[(rr + 8) * SPITCH + cc + 1] = acc[mt][nt][3];
        }
    }
}

#define ZERO_ACC(acc) { \
    _Pragma("unroll") for (int i = 0; i < 2; i++) \
    _Pragma("unroll") for (int j = 0; j < 4; j++) \
    _Pragma("unroll") for (int t = 0; t < 4; t++) acc[i][j][t] = 0.f; }

#define ISSUEA(Abase, lda, k0, bofs) { \
    _Pragma("unroll") for (int rep = 0; rep < 4; rep++) { \
        int lin = rep * 256 + tid; int r = lin >> 3, c4 = (lin & 7) * 4; \
        CP16(su + ((bofs) + r * APITCH + c4) * 4, \
             &(Abase)[(long)(row0 + r) * (lda) + (k0) + c4]); } }
#define ISSUEB(Bbase, ldb, k0, c0, bofs) { \
    _Pragma("unroll") for (int rep = 0; rep < 8; rep++) { \
        int lin = rep * 256 + tid; int kk = lin >> 6, n = lin & 63; \
        CP4(su + ((bofs) + n * BPITCH + kk) * 4, \
            &(Bbase)[(long)((k0) + kk) * (ldb) + (c0) + n]); } }

// ---------------- adaLN fused dual GEMM (cp.async double-buffered) -----------
#define ADA_STRIDE (A_WORDS + 2 * B_WORDS)            // 9216 words
#define ADA_SMEM (2 * ADA_STRIDE * 4)                 // 73728 B
__global__ void __launch_bounds__(256, 2)
gemm_ada(const float* __restrict__ Wg_, const float* __restrict__ Wo_,
         const float* __restrict__ badag) {
    extern __shared__ float sm[];
    uint32_t su = smem_u32(sm);

    int tid = threadIdx.x, wid = tid >> 5;
    int g4 = (tid & 31) >> 2, q4 = tid & 3;
    int wr = (wid & 3) * 32, wc = (wid >> 2) * 32;
    int row0 = blockIdx.y * 128, col0 = blockIdx.x * 64;
    const float* A = g_sn;

    float acc1[2][4][4], acc2[2][4][4];
    ZERO_ACC(acc1); ZERO_ACC(acc2);

    ISSUEA(A, CS, 0, 0);
    ISSUEB(Wg_, CA, 0, col0, A_WORDS);
    ISSUEB(Wo_, CA, 0, col0, A_WORDS + B_WORDS);
    CP_COMMIT();
    const int KT = CS / 32;
    for (int kt = 0; kt < KT; kt++) {
        int cur = (kt & 1) * ADA_STRIDE;
        if (kt + 1 < KT) {
            int nxt = ((kt + 1) & 1) * ADA_STRIDE;
            int k0 = (kt + 1) * 32;
            ISSUEA(A, CS, k0, nxt);
            ISSUEB(Wg_, CA, k0, col0, nxt + A_WORDS);
            ISSUEB(Wo_, CA, k0, col0, nxt + A_WORDS + B_WORDS);
            CP_COMMIT();
            CP_WAIT1();
        } else { CP_WAIT0(); }
        __syncthreads();
        frag_compute2_cvt(sm + cur, sm + cur + A_WORDS, sm + cur + A_WORDS + B_WORDS,
                          acc1, acc2, wr, wc, g4, q4);
        __syncthreads();
    }

    float* st1 = sm;
    float* st2 = sm + STAGE_WORDS;
    stage_acc(st1, acc1, wr, wc, g4, q4);
    stage_acc(st2, acc2, wr, wc, g4, q4);
    __syncthreads();
    #pragma unroll
    for (int rep = 0; rep < 32; rep++) {
        int idx = rep * 256 + tid;
        int r = idx >> 6, c = idx & 63;
        int m = row0 + r, n = col0 + c;
        float v1 = st1[r * SPITCH + c], v2 = st2[r * SPITCH + c];
        g_an[(long)m * CA + n] = sigmoidf_(v1 + badag[n]) * g_lna[(long)m * CA + n] + v2;
    }
}

// ---------------- fused 4-way projection GEMM (cp.async double-buffered) -----
#define GM_STRIDE (A_WORDS + B_WORDS)                 // 6912 words
#define PROJ_SMEM (2 * GM_STRIDE * 4)                 // 55296 B
__global__ void __launch_bounds__(256, 3)
gemm_proj4(const float* __restrict__ Wq, const float* __restrict__ Wk,
           const float* __restrict__ Wv, const float* __restrict__ Wg_,
           const float* __restrict__ bq) {
    extern __shared__ float sm[];
    uint32_t su = smem_u32(sm);

    int tid = threadIdx.x, wid = tid >> 5;
    int g4 = (tid & 31) >> 2, q4 = tid & 3;
    int wr = (wid & 3) * 32, wc = (wid >> 2) * 32;
    int row0 = blockIdx.y * 128;
    int cg = blockIdx.x * 64;
    int w = cg / CA, coln = cg % CA;
    const float* B = (w == 0) ? Wq : (w == 1) ? Wk : (w == 2) ? Wv : Wg_;
    const float* A = g_an;

    float acc[2][4][4];
    ZERO_ACC(acc);

    ISSUEA(A, CA, 0, 0);
    ISSUEB(B, CA, 0, coln, A_WORDS);
    CP_COMMIT();
    const int KT = CA / 32;
    for (int kt = 0; kt < KT; kt++) {
        int cur = (kt & 1) * GM_STRIDE;
        if (kt + 1 < KT) {
            int nxt = ((kt + 1) & 1) * GM_STRIDE;
            int k0 = (kt + 1) * 32;
            ISSUEA(A, CA, k0, nxt);
            ISSUEB(B, CA, k0, coln, nxt + A_WORDS);
            CP_COMMIT();
            CP_WAIT1();
        } else { CP_WAIT0(); }
        __syncthreads();
        frag_compute_cvt(sm + cur, sm + cur + A_WORDS, acc, wr, wc, g4, q4);
        __syncthreads();
    }

    float* st = sm;
    stage_acc(st, acc, wr, wc, g4, q4);
    __syncthreads();
    float* dst = (w == 0) ? g_q : (w == 1) ? g_k : g_v;
    #pragma unroll
    for (int rep = 0; rep < 32; rep++) {
        int idx = rep * 256 + tid;
        int r = idx >> 6, c = idx & 63;
        int m = row0 + r, n = coln + c;
        float v = st[r * SPITCH + c];
        if (w == 3) {
            g_gate[(long)m * CA + n] = v;
        } else {
            if (w == 0) v += bq[n];
            int b = m / SS, si = m % SS, h = n / HD, d = n % HD;
            dst[(((long)(b * HH + h) * SS) + si) * HD + d] = v;
        }
    }
}

// ---------------- fused output GEMM (cp.async double-buffered) ---------------
__global__ void __launch_bounds__(256, 2)
gemm_final(const float* __restrict__ Wout, const float* __restrict__ s_,
           const float* __restrict__ Wsg, const float* __restrict__ bsg,
           float* __restrict__ out) {
    extern __shared__ float sm[];
    uint32_t su = smem_u32(sm);

    int tid = threadIdx.x, wid = tid >> 5;
    int g4 = (tid & 31) >> 2, q4 = tid & 3;
    int wr = (wid & 3) * 32, wc = (wid >> 2) * 32;
    int row0 = blockIdx.y * 128, col0 = blockIdx.x * 64;

    float acc1[2][4][4], acc2[2][4][4];
    ZERO_ACC(acc1); ZERO_ACC(acc2);

    {
        const float* A = g_go;
        ISSUEA(A, CA, 0, 0);
        ISSUEB(Wout, CA, 0, col0, A_WORDS);
        CP_COMMIT();
        const int KT = CA / 32;
        for (int kt = 0; kt < KT; kt++) {
            int cur = (kt & 1) * GM_STRIDE;
            if (kt + 1 < KT) {
                int nxt = ((kt + 1) & 1) * GM_STRIDE;
                int k0 = (kt + 1) * 32;
                ISSUEA(A, CA, k0, nxt);
                ISSUEB(Wout, CA, k0, col0, nxt + A_WORDS);
                CP_COMMIT();
                CP_WAIT1();
            } else { CP_WAIT0(); }
            __syncthreads();
            frag_compute_cvt(sm + cur, sm + cur + A_WORDS, acc1, wr, wc, g4, q4);
            __syncthreads();
        }
    }
    {
        ISSUEA(s_, CS, 0, 0);
        ISSUEB(Wsg, CA, 0, col0, A_WORDS);
        CP_COMMIT();
        const int KT = CS / 32;
        for (int kt = 0; kt < KT; kt++) {
            int cur = (kt & 1) * GM_STRIDE;
            if (kt + 1 < KT) {
                int nxt = ((kt + 1) & 1) * GM_STRIDE;
                int k0 = (kt + 1) * 32;
                ISSUEA(s_, CS, k0, nxt);
                ISSUEB(Wsg, CA, k0, col0, nxt + A_WORDS);
                CP_COMMIT();
                CP_WAIT1();
            } else { CP_WAIT0(); }
            __syncthreads();
            frag_compute_cvt(sm + cur, sm + cur + A_WORDS, acc2, wr, wc, g4, q4);
            __syncthreads();
        }
    }

    #pragma unroll
    for (int mt = 0; mt < 2; mt++)
        #pragma unroll
        for (int nt = 0; nt < 4; nt++)
            #pragma unroll
            for (int t = 0; t < 4; t++) {
                int n = col0 + wc + nt * 8 + 2 * q4 + (t & 1);
                acc1[mt][nt][t] *= sigmoidf_(acc2[mt][nt][t] + __ldg(&bsg[n]));
            }

    float* st = sm;
    stage_acc(st, acc1, wr, wc, g4, q4);
    __syncthreads();
    #pragma unroll
    for (int rep = 0; rep < 32; rep++) {
        int idx = rep * 256 + tid;
        int r = idx >> 6, c = idx & 63;
        out[(long)(row0 + r) * CA + col0 + c] = st[r * SPITCH + c];
    }
}

// ---------------- pair bias v6: bf16 m16n8k16 MMA ----------------------------
#define WP 68
#define PB_Z_WORDS (64 * WP)                         // 4352
#define PB_WB_OFF  PB_Z_WORDS
#define PB_SMEM ((PB_Z_WORDS + 16 * WP) * 4)         // 21760 B
__global__ void __launch_bounds__(256)
pairbias6_kernel(const float* __restrict__ z, const float* __restrict__ beta,
                 const float* __restrict__ Wb, const float* __restrict__ gz,
                 const float* __restrict__ bz) {
    extern __shared__ float smf[];
    uint32_t* Z16  = (uint32_t*)smf;           // [64][WP] bf16x2
    uint32_t* Wb16 = Z16 + PB_WB_OFF;          // [16][WP] bf16x2
    float*    res  = smf;                      // aliased over Z16 after MMA
    __shared__ float gzs[CZ], bzs[CZ];

    int tid = threadIdx.x, wid = tid >> 5, lane = tid & 31;
    int g4 = lane >> 2, q4 = lane & 3;
    int b = blockIdx.z, p = blockIdx.y, q0 = blockIdx.x * 64;

    const float* zb = z + ((long)(b * SS + p) * SS + q0) * CZ;
    const float* betab = beta + ((long)(b * SS + p) * SS + q0) * HH;

    float betar[4];
    #pragma unroll
    for (int rep = 0; rep < 4; rep++)
        betar[rep] = betab[rep * 256 + tid];

    for (int idx = tid; idx < (CZ / 2) * HH; idx += 256) {
        int j = idx >> 4, h = idx & 15;
        Wb16[h * WP + j] = pack_bf16x2(Wb[(2 * j) * HH + h], Wb[(2 * j + 1) * HH + h]);
    }
    for (int idx = tid; idx < CZ; idx += 256) { gzs[idx] = gz[idx]; bzs[idx] = bz[idx]; }
    __syncthreads();

    {
        float4 vr[8];
        #pragma unroll
        for (int rr = 0; rr < 8; rr++) {
            int pl = wid * 8 + rr;
            vr[rr] = *(const float4*)&zb[(long)pl * CZ + lane * 4];
        }
        float sums[8], sqs[8];
        #pragma unroll
        for (int rr = 0; rr < 8; rr++) {
            float4 v = vr[rr];
            sums[rr] = v.x + v.y + v.z + v.w;
            sqs[rr]  = v.x * v.x + v.y * v.y + v.z * v.z + v.w * v.w;
        }
        #pragma unroll
        for (int o = 16; o; o >>= 1) {
            #pragma unroll
            for (int rr = 0; rr < 8; rr++) {
                sums[rr] += __shfl_xor_sync(0xffffffffu, sums[rr], o);
                sqs[rr]  += __shfl_xor_sync(0xffffffffu, sqs[rr],  o);
            }
        }
        #pragma unroll
        for (int rr = 0; rr < 8; rr++) {
            int pl = wid * 8 + rr;
            float mean = sums[rr] * (1.0f / CZ);
            float var  = sqs[rr] * (1.0f / CZ) - mean * mean;
            float rstd = rsqrtf(var + EPS);
            float4 v = vr[rr];
            int c = lane * 4;
            float z0 = (v.x - mean) * rstd * gzs[c + 0] + bzs[c + 0];
            float z1 = (v.y - mean) * rstd * gzs[c + 1] + bzs[c + 1];
            float z2 = (v.z - mean) * rstd * gzs[c + 2] + bzs[c + 2];
            float z3 = (v.w - mean) * rstd * gzs[c + 3] + bzs[c + 3];
            uint2 o2;
            o2.x = pack_bf16x2(z0, z1);
            o2.y = pack_bf16x2(z2, z3);
            *(uint2*)&Z16[pl * WP + lane * 2] = o2;
        }
    }
    __syncthreads();

    float acc[4];
    #pragma unroll
    for (int t = 0; t < 4; t++) acc[t] = 0.f;
    {
        int wr = (wid & 3) * 16;
        int hb = (wid >> 2) * 8;
        #pragma unroll
        for (int kc = 0; kc < 8; kc++) {
            int kb = kc * 8 + q4;
            uint32_t af[4];
            af[0] = Z16[(wr + g4) * WP + kb];
            af[1] = Z16[(wr + g4 + 8) * WP + kb];
            af[2] = Z16[(wr + g4) * WP + kb + 4];
            af[3] = Z16[(wr + g4 + 8) * WP + kb + 4];
            uint32_t bf[2];
            bf[0] = Wb16[(hb + g4) * WP + kb];
            bf[1] = Wb16[(hb + g4) * WP + kb + 4];
            mma_bf16(acc, af, bf);
        }
    }
    __syncthreads();

    {
        int wr = (wid & 3) * 16;
        int hb = (wid >> 2) * 8;
        #pragma unroll
        for (int t = 0; t < 4; t++) {
            int row = wr + g4 + ((t >= 2) ? 8 : 0);
            int h = hb + 2 * q4 + (t & 1);
            res[row * 17 + h] = acc[t];
        }
    }
    __syncthreads();

    #pragma unroll
    for (int rep = 0; rep < 4; rep++) {
        int idx = rep * 256 + tid;
        int ql = idx >> 4, hh = idx & 15;
        res[ql * 17 + hh] += betar[rep];
    }
    __syncthreads();

    #pragma unroll
    for (int rep = 0; rep < 4; rep++) {
        int idx = rep * 256 + tid;
        int h = idx >> 6, ql = idx & 63;
        g_bias[(((long)(b * HH + h) * SS) + p) * SS + q0 + ql] = res[ql * 17 + h];
    }
}

// ---------------- fused attention: pipelined K/V, direct-gmem bias -----------
#define QP 52
#define KP 52
#define VP 68
#define PP 68
#define AT_K (128 * QP)
#define AT_V (AT_K + 64 * KP)
#define AT_PB (AT_V + 48 * VP)
#define AT_WORDS (AT_PB + 128 * PP)
#define ATT_SMEM (AT_WORDS * 4)              // 87808 B

__global__ void __launch_bounds__(256, 2)
attn_kernel(const float* __restrict__ qg, const float* __restrict__ kg,
            const float* __restrict__ vg, const float* __restrict__ biasg,
            const float* __restrict__ gateg, float* __restrict__ outg) {
    extern __shared__ char smem[];
    uint32_t* Qs = (uint32_t*)smem;
    uint32_t* Ks = Qs + AT_K;
    uint32_t* Vs = Qs + AT_V;
    uint32_t* Ps = Qs + AT_PB;

    int tid = threadIdx.x, wid = tid >> 5, lane = tid & 31;
    int g4 = lane >> 2, q4 = lane & 3;
    int bh = blockIdx.y;
    int b = bh >> 4, h = bh & 15;
    int i0 = blockIdx.x * 128;
    const float* qb = qg + ((long)bh * SS + i0) * HD;
    const float* kb_ = kg + (long)bh * SS * HD;
    const float* vb = vg + (long)bh * SS * HD;
    const float* biasb = biasg + (long)bh * SS * SS;   // [j][i]

    #pragma unroll
    for (int rep = 0; rep < 6; rep++) {
        int idx = rep * 256 + tid;
        int r = idx / 12, c4 = (idx % 12) * 4;
        float4 v = *(const float4*)&qb[(long)r * HD + c4];
        uint32_t* d = &Qs[r * QP + c4];
        d[0] = f2tf32(v.x); d[1] = f2tf32(v.y); d[2] = f2tf32(v.z); d[3] = f2tf32(v.w);
    }

    int wr = wid * 16;
    float accO[6][4];
    #pragma unroll
    for (int n = 0; n < 6; n++)
        #pragma unroll
        for (int t = 0; t < 4; t++) accO[n][t] = 0.f;
    float mrow[2] = {-1e30f, -1e30f};
    float lrow[2] = {0.f, 0.f};

    float4 pk[3]; float pv[12];
    #pragma unroll
    for (int rep = 0; rep < 3; rep++) {
        int idx = rep * 256 + tid;
        int r = idx / 12, c4 = (idx % 12) * 4;
        pk[rep] = *(const float4*)&kb_[(long)r * HD + c4];
    }
    #pragma unroll
    for (int rep = 0; rep < 12; rep++) {
        int idx = rep * 256 + tid;
        int r = idx / 48, d = idx % 48;
        pv[rep] = vb[(long)r * HD + d];
    }

    for (int j = 0; j < 12; j++) {
        __syncthreads();
        #pragma unroll
        for (int rep = 0; rep < 3; rep++) {
            int idx = rep * 256 + tid;
            int r = idx / 12, c4 = (idx % 12) * 4;
            uint32_t* d = &Ks[r * KP + c4];
            d[0] = f2tf32(pk[rep].x); d[1] = f2tf32(pk[rep].y);
            d[2] = f2tf32(pk[rep].z); d[3] = f2tf32(pk[rep].w);
        }
        #pragma unroll
        for (int rep = 0; rep < 12; rep++) {
            int idx = rep * 256 + tid;
            int r = idx / 48, d = idx % 48;
            Vs[d * VP + r] = f2tf32(pv[rep]);
        }
        __syncthreads();
        if (j + 1 < 12) {
            #pragma unroll
            for (int rep = 0; rep < 3; rep++) {
                int idx = rep * 256 + tid;
                int r = idx / 12, c4 = (idx % 12) * 4;
                pk[rep] = *(const float4*)&kb_[(long)((j + 1) * 64 + r) * HD + c4];
            }
            #pragma unroll
            for (int rep = 0; rep < 12; rep++) {
                int idx = rep * 256 + tid;
                int r = idx / 48, d = idx % 48;
                pv[rep] = vb[(long)((j + 1) * 64 + r) * HD + d];
            }
        }

        float S[8][4];
        #pragma unroll
        for (int nt = 0; nt < 8; nt++)
            #pragma unroll
            for (int t = 0; t < 4; t++) S[nt][t] = 0.f;
        #pragma unroll
        for (int kc = 0; kc < 6; kc++) {
            int kbx = kc * 8 + q4;
            uint32_t af[4];
            af[0] = Qs[(wr + g4) * QP + kbx];
            af[1] = Qs[(wr + g4 + 8) * QP + kbx];
            af[2] = Qs[(wr + g4) * QP + kbx + 4];
            af[3] = Qs[(wr + g4 + 8) * QP + kbx + 4];
            #pragma unroll
            for (int nt = 0; nt < 8; nt++) {
                uint32_t bf2[2];
                bf2[0] = Ks[(nt * 8 + g4) * KP + kbx];
                bf2[1] = Ks[(nt * 8 + g4) * KP + kbx + 4];
                mma_tf32(S[nt], af, bf2);
            }
        }
        const float* bj = biasb + (long)(j * 64) * SS + i0;
        int r0 = wr + g4, r1 = r0 + 8;
        float mn0 = mrow[0], mn1 = mrow[1];
        #pragma unroll
        for (int nt = 0; nt < 8; nt++) {
            #pragma unroll
            for (int t = 0; t < 4; t++) {
                int rr = (t >= 2) ? r1 : r0;
                int cc = nt * 8 + 2 * q4 + (t & 1);
                float val = S[nt][t] * SCALE + __ldg(&bj[(long)cc * SS + rr]);
                S[nt][t] = val;
                if (t < 2) mn0 = fmaxf(mn0, val); else mn1 = fmaxf(mn1, val);
            }
        }
        mn0 = fmaxf(mn0, __shfl_xor_sync(0xffffffffu, mn0, 1));
        mn0 = fmaxf(mn0, __shfl_xor_sync(0xffffffffu, mn0, 2));
        mn1 = fmaxf(mn1, __shfl_xor_sync(0xffffffffu, mn1, 1));
        mn1 = fmaxf(mn1, __shfl_xor_sync(0xffffffffu, mn1, 2));
        float al0 = __expf(mrow[0] - mn0);
        float al1 = __expf(mrow[1] - mn1);
        mrow[0] = mn0; mrow[1] = mn1;
        float s0 = 0.f, s1 = 0.f;
        #pragma unroll
        for (int nt = 0; nt < 8; nt++) {
            #pragma unroll
            for (int t = 0; t < 4; t++) {
                float p = __expf(S[nt][t] - ((t >= 2) ? mn1 : mn0));
                S[nt][t] = p;
                if (t < 2) s0 += p; else s1 += p;
                int rr = (t >= 2) ? r1 : r0;
                int cc = nt * 8 + 2 * q4 + (t & 1);
                Ps[rr * PP + cc] = f2tf32(p);
            }
        }
        s0 += __shfl_xor_sync(0xffffffffu, s0, 1);
        s0 += __shfl_xor_sync(0xffffffffu, s0, 2);
        s1 += __shfl_xor_sync(0xffffffffu, s1, 1);
        s1 += __shfl_xor_sync(0xffffffffu, s1, 2);
        lrow[0] = lrow[0] * al0 + s0;
        lrow[1] = lrow[1] * al1 + s1;
        #pragma unroll
        for (int n = 0; n < 6; n++) {
            accO[n][0] *= al0; accO[n][1] *= al0;
            accO[n][2] *= al1; accO[n][3] *= al1;
        }
        __syncwarp();
        #pragma unroll
        for (int kc = 0; kc < 8; kc++) {
            int kbx = kc * 8 + q4;
            uint32_t af[4];
            af[0] = Ps[(wr + g4) * PP + kbx];
            af[1] = Ps[(wr + g4 + 8) * PP + kbx];
            af[2] = Ps[(wr + g4) * PP + kbx + 4];
            af[3] = Ps[(wr + g4 + 8) * PP + kbx + 4];
            #pragma unroll
            for (int n = 0; n < 6; n++) {
                uint32_t bf2[2];
                bf2[0] = Vs[(n * 8 + g4) * VP + kbx];
                bf2[1] = Vs[(n * 8 + g4) * VP + kbx + 4];
                mma_tf32(accO[n], af, bf2);
            }
        }
    }

    float inv0 = 1.0f / lrow[0], inv1 = 1.0f / lrow[1];
    #pragma unroll
    for (int n = 0; n < 6; n++) {
        #pragma unroll
        for (int t = 0; t < 4; t++) {
            int r = wr + g4 + ((t >= 2) ? 8 : 0);
            int c = n * 8 + 2 * q4 + (t & 1);
            long gi = ((long)(b * SS + i0 + r)) * CA + h * HD + c;
            float o = accO[n][t] * ((t >= 2) ? inv1 : inv0);
            outg[gi] = o * sigmoidf_(gateg[gi]);
        }
    }
}

// ---------------- host side --------------------------------------------------
static float* sym(const void* symbol) {
    void* p = nullptr;
    cudaGetSymbolAddress(&p, symbol);
    return (float*)p;
}

// second stream + fork/join events, created once at load time (host objects
// only; no device memory allocation). g_streamsOk records whether init
// succeeded — kernel_launch falls back to the serial schedule otherwise.
static cudaStream_t g_s2 = nullptr;
static cudaEvent_t  g_evFork = nullptr, g_evJoin = nullptr;
static bool g_streamsOk = false;
static struct StreamInit {
    StreamInit() {
        g_streamsOk =
            cudaStreamCreateWithFlags(&g_s2, cudaStreamNonBlocking) == cudaSuccess &&
            cudaEventCreateWithFlags(&g_evFork, cudaEventDisableTiming) == cudaSuccess &&
            cudaEventCreateWithFlags(&g_evJoin, cudaEventDisableTiming) == cudaSuccess;
    }
} g_streamInit;

extern "C" void kernel_launch(void* const* d_in, const int* in_sizes, int n_in,
                              void* d_out, int out_size) {
    const float* a        = (const float*)d_in[0];
    const float* s        = (const float*)d_in[1];
    const float* z        = (const float*)d_in[2];
    const float* beta     = (const float*)d_in[3];
    const float* gamma_s  = (const float*)d_in[4];
    const float* W_ada_g  = (const float*)d_in[5];
    const float* b_ada_g  = (const float*)d_in[6];
    const float* W_ada_o  = (const float*)d_in[7];
    const float* Wq       = (const float*)d_in[8];
    const float* bq       = (const float*)d_in[9];
    const float* Wk       = (const float*)d_in[10];
    const float* Wv       = (const float*)d_in[11];
    const float* Wb       = (const float*)d_in[12];
    const float* gz       = (const float*)d_in[13];
    const float* bz       = (const float*)d_in[14];
    const float* Wg       = (const float*)d_in[15];
    const float* Wout     = (const float*)d_in[16];
    const float* Ws_gate  = (const float*)d_in[17];
    const float* bs_gate  = (const float*)d_in[18];
    float* out = (float*)d_out;

    float* p_q    = sym(g_q);
    float* p_k    = sym(g_k);
    float* p_v    = sym(g_v);
    float* p_gate = sym(g_gate);
    float* p_bias = sym(g_bias);
    float* p_go   = sym(g_go);

    cudaFuncSetAttribute(gemm_ada,        cudaFuncAttributeMaxDynamicSharedMemorySize, ADA_SMEM);
    cudaFuncSetAttribute(gemm_proj4,      cudaFuncAttributeMaxDynamicSharedMemorySize, PROJ_SMEM);
    cudaFuncSetAttribute(gemm_final,      cudaFuncAttributeMaxDynamicSharedMemorySize, PROJ_SMEM);
    cudaFuncSetAttribute(pairbias6_kernel,cudaFuncAttributeMaxDynamicSharedMemorySize, PB_SMEM);
    cudaFuncSetAttribute(attn_kernel,     cudaFuncAttributeMaxDynamicSharedMemorySize, ATT_SMEM);

    if (g_streamsOk) {
        // fork: branch A (pairbias, s2) || branch B (ln->ada->proj4, default)
        cudaEventRecord(g_evFork, (cudaStream_t)0);
        cudaStreamWaitEvent(g_s2, g_evFork, 0);
        pairbias6_kernel<<<dim3(SS / 64, SS, BB), 256, PB_SMEM, g_s2>>>(z, beta, Wb, gz, bz);
        cudaEventRecord(g_evJoin, g_s2);

        ln_kernel<<<MM, 256>>>(s, a, gamma_s);
        gemm_ada<<<dim3(CA / 64, MM / 128), 256, ADA_SMEM>>>(W_ada_g, W_ada_o, b_ada_g);
        gemm_proj4<<<dim3(4 * CA / 64, MM / 128), 256, PROJ_SMEM>>>(Wq, Wk, Wv, Wg, bq);

        // join: attn needs both branches
        cudaStreamWaitEvent((cudaStream_t)0, g_evJoin, 0);
    } else {
        // serial fallback (R13 schedule)
        ln_kernel<<<MM, 256>>>(s, a, gamma_s);
        gemm_ada<<<dim3(CA / 64, MM / 128), 256, ADA_SMEM>>>(W_ada_g, W_ada_o, b_ada_g);
        gemm_proj4<<<dim3(4 * CA / 64, MM / 128), 256, PROJ_SMEM>>>(Wq, Wk, Wv, Wg, bq);
        pairbias6_kernel<<<dim3(SS / 64, SS, BB), 256, PB_SMEM>>>(z, beta, Wb, gz, bz);
    }

    attn_kernel<<<dim3(SS / 128, BB * HH), 256, ATT_SMEM>>>(p_q, p_k, p_v, p_bias, p_gate, p_go);
    gemm_final<<<dim3(CA / 64, MM / 128), 256, PROJ_SMEM>>>(Wout, s, Ws_gate, bs_gate, out);
}

// round 16
// speedup vs baseline: 1.4369x; 1.4369x over previous
#include <cuda_runtime.h>
#include <cuda_bf16.h>
#include <math.h>
#include <cstdint>

// Problem constants
#define BB   2
#define SS   768
#define CA   768
#define CS   384
#define CZ   128
#define HH   16
#define HD   48
#define MM   (BB*SS)          // 1536
#define EPS  1e-5f
#define SCALE (0.14433756729740643f)  // 1/sqrt(48)

// ---------------- scratch (device globals) ----------------------------------
__device__ float g_sn   [MM*CS];
__device__ float g_lna  [MM*CA];
__device__ float g_an   [MM*CA];
__device__ float g_q    [BB*HH*SS*HD];      // [b,h,s,d]
__device__ float g_k    [BB*HH*SS*HD];      // [b,h,s,d]
__device__ float g_v    [BB*HH*SS*HD];      // [b,h,s,d]
__device__ float g_gate [MM*CA];
__device__ float g_bias [BB*HH*SS*SS];      // pair bias, layout [b,h,j,i] (i contiguous)
__device__ float g_go   [MM*CA];

// ---------------- helpers ----------------------------------------------------
__device__ __forceinline__ float sigmoidf_(float x) { return 1.0f / (1.0f + expf(-x)); }

__device__ __forceinline__ uint32_t f2tf32(float f) {
    uint32_t r;
    asm("cvt.rna.tf32.f32 %0, %1;" : "=r"(r) : "f"(f));
    return r;
}
__device__ __forceinline__ uint32_t pack_bf16x2(float lo, float hi) {
    uint32_t r;
    asm("cvt.rn.bf16x2.f32 %0, %1, %2;" : "=r"(r) : "f"(hi), "f"(lo));
    return r;
}
__device__ __forceinline__ uint32_t smem_u32(const void* p) {
    uint32_t a;
    asm("{ .reg .u64 t; cvta.to.shared.u64 t, %1; cvt.u32.u64 %0, t; }"
        : "=r"(a) : "l"(p));
    return a;
}

#define CP16(dst, src) asm volatile("cp.async.ca.shared.global [%0], [%1], 16;" :: "r"(dst), "l"(src))
#define CP4(dst, src)  asm volatile("cp.async.ca.shared.global [%0], [%1], 4;"  :: "r"(dst), "l"(src))
#define CP_COMMIT()    asm volatile("cp.async.commit_group;" ::: "memory")
#define CP_WAIT1()     asm volatile("cp.async.wait_group 1;" ::: "memory")
#define CP_WAIT0()     asm volatile("cp.async.wait_group 0;" ::: "memory")

__device__ __forceinline__ void mma_tf32(float* d, const uint32_t* a, const uint32_t* b) {
    asm volatile("mma.sync.aligned.m16n8k8.row.col.f32.tf32.tf32.f32 "
        "{%0,%1,%2,%3}, {%4,%5,%6,%7}, {%8,%9}, {%0,%1,%2,%3};"
        : "+f"(d[0]), "+f"(d[1]), "+f"(d[2]), "+f"(d[3])
        : "r"(a[0]), "r"(a[1]), "r"(a[2]), "r"(a[3]), "r"(b[0]), "r"(b[1]));
}
__device__ __forceinline__ void mma_bf16(float* d, const uint32_t* a, const uint32_t* b) {
    asm volatile("mma.sync.aligned.m16n8k16.row.col.f32.bf16.bf16.f32 "
        "{%0,%1,%2,%3}, {%4,%5,%6,%7}, {%8,%9}, {%0,%1,%2,%3};"
        : "+f"(d[0]), "+f"(d[1]), "+f"(d[2]), "+f"(d[3])
        : "r"(a[0]), "r"(a[1]), "r"(a[2]), "r"(a[3]), "r"(b[0]), "r"(b[1]));
}

__device__ float2 blockReduceSum2(float a, float b) {
    __shared__ float sa[32], sb[32];
    int lane = threadIdx.x & 31, wid = threadIdx.x >> 5;
    #pragma unroll
    for (int o = 16; o; o >>= 1) {
        a += __shfl_xor_sync(0xffffffffu, a, o);
        b += __shfl_xor_sync(0xffffffffu, b, o);
    }
    if (lane == 0) { sa[wid] = a; sb[wid] = b; }
    __syncthreads();
    if (wid == 0) {
        int nw = (blockDim.x + 31) >> 5;
        a = (lane < nw) ? sa[lane] : 0.0f;
        b = (lane < nw) ? sb[lane] : 0.0f;
        #pragma unroll
        for (int o = 16; o; o >>= 1) {
            a += __shfl_xor_sync(0xffffffffu, a, o);
            b += __shfl_xor_sync(0xffffffffu, b, o);
        }
        if (lane == 0) { sa[0] = a; sb[0] = b; }
    }
    __syncthreads();
    float2 r = make_float2(sa[0], sb[0]);
    __syncthreads();
    return r;
}

// ---------------- LN kernel --------------------------------------------------
__global__ void ln_kernel(const float* __restrict__ s, const float* __restrict__ a,
                          const float* __restrict__ gamma_s) {
    int r = blockIdx.x;
    int tid = threadIdx.x;
    const float* srow = s + (long)r * CS;
    float sum = 0.f, sq = 0.f;
    for (int c = tid; c < CS; c += blockDim.x) { float v = srow[c]; sum += v; sq += v * v; }
    float2 t = blockReduceSum2(sum, sq);
    float mean = t.x / CS, var = t.y / CS - mean * mean;
    float rstd = rsqrtf(var + EPS);
    for (int c = tid; c < CS; c += blockDim.x)
        g_sn[(long)r * CS + c] = (srow[c] - mean) * rstd * gamma_s[c];

    const float* arow = a + (long)r * CA;
    sum = 0.f; sq = 0.f;
    for (int c = tid; c < CA; c += blockDim.x) { float v = arow[c]; sum += v; sq += v * v; }
    t = blockReduceSum2(sum, sq);
    mean = t.x / CA; var = t.y / CA - mean * mean;
    rstd = rsqrtf(var + EPS);
    for (int c = tid; c < CA; c += blockDim.x)
        g_lna[(long)r * CA + c] = (arow[c] - mean) * rstd;
}

// ---------------- common GEMM machinery (128x64 tile, BK=32, cp.async) ------
#define APITCH 36
#define BPITCH 36
#define A_WORDS (128 * APITCH)               // 4608
#define B_WORDS (64 * BPITCH)                // 2304
#define SPITCH 68
#define STAGE_WORDS (128 * SPITCH)           // 8704

__device__ __forceinline__ void frag_compute_cvt(const float* As, const float* Bs,
        float (&acc)[2][4][4], int wr, int wc, int g4, int q4) {
    #pragma unroll
    for (int kc = 0; kc < 4; kc++) {
        int kb = kc * 8 + q4;
        uint32_t af[2][4];
        #pragma unroll
        for (int mt = 0; mt < 2; mt++) {
            int r = wr + mt * 16 + g4;
            af[mt][0] = f2tf32(As[r * APITCH + kb]);
            af[mt][1] = f2tf32(As[(r + 8) * APITCH + kb]);
            af[mt][2] = f2tf32(As[r * APITCH + kb + 4]);
            af[mt][3] = f2tf32(As[(r + 8) * APITCH + kb + 4]);
        }
        #pragma unroll
        for (int nt = 0; nt < 4; nt++) {
            int c = wc + nt * 8 + g4;
            uint32_t bf[2] = {f2tf32(Bs[c * BPITCH + kb]), f2tf32(Bs[c * BPITCH + kb + 4])};
            #pragma unroll
            for (int mt = 0; mt < 2; mt++)
                mma_tf32(acc[mt][nt], af[mt], bf);
        }
    }
}

__device__ __forceinline__ void frag_compute2_cvt(const float* As, const float* Bs1,
        const float* Bs2, float (&acc1)[2][4][4], float (&acc2)[2][4][4],
        int wr, int wc, int g4, int q4) {
    #pragma unroll
    for (int kc = 0; kc < 4; kc++) {
        int kb = kc * 8 + q4;
        uint32_t af[2][4];
        #pragma unroll
        for (int mt = 0; mt < 2; mt++) {
            int r = wr + mt * 16 + g4;
            af[mt][0] = f2tf32(As[r * APITCH + kb]);
            af[mt][1] = f2tf32(As[(r + 8) * APITCH + kb]);
            af[mt][2] = f2tf32(As[r * APITCH + kb + 4]);
            af[mt][3] = f2tf32(As[(r + 8) * APITCH + kb + 4]);
        }
        #pragma unroll
        for (int nt = 0; nt < 4; nt++) {
            int c = wc + nt * 8 + g4;
            uint32_t b1[2] = {f2tf32(Bs1[c * BPITCH + kb]), f2tf32(Bs1[c * BPITCH + kb + 4])};
            uint32_t b2[2] = {f2tf32(Bs2[c * BPITCH + kb]), f2tf32(Bs2[c * BPITCH + kb + 4])};
            #pragma unroll
            for (int mt = 0; mt < 2; mt++) {
                mma_tf32(acc1[mt][nt], af[mt], b1);
                mma_tf32(acc2[mt][nt], af[mt], b2);
            }
        }
    }
}

__device__ __forceinline__ void stage_acc(float* st, const float (&acc)[2][4][4],
        int wr, int wc, int g4, int q4) {
    #pragma unroll
    for (int mt = 0; mt < 2; mt++) {
        #pragma unroll
        for (int nt = 0; nt < 4; nt++) {
            int rr = wr + mt * 16 + g4;
            int cc = wc + nt * 8 + 2 * q4;
            st[rr * SPITCH + cc]           = acc[mt][nt][0];
            st[rr * SPITCH + cc + 1]       = acc[mt][nt][1];
            st[(rr + 8) * SPITCH + cc]     = acc[mt][nt][2];
            st[(rr + 8) * SPITCH + cc + 1] = acc[mt][nt][3];
        }
    }
}

#define ZERO_ACC(acc) { \
    _Pragma("unroll") for (int i = 0; i < 2; i++) \
    _Pragma("unroll") for (int j = 0; j < 4; j++) \
    _Pragma("unroll") for (int t = 0; t < 4; t++) acc[i][j][t] = 0.f; }

#define ISSUEA(Abase, lda, k0, bofs) { \
    _Pragma("unroll") for (int rep = 0; rep < 4; rep++) { \
        int lin = rep * 256 + tid; int r = lin >> 3, c4 = (lin & 7) * 4; \
        CP16(su + ((bofs) + r * APITCH + c4) * 4, \
             &(Abase)[(long)(row0 + r) * (lda) + (k0) + c4]); } }
#define ISSUEB(Bbase, ldb, k0, c0, bofs) { \
    _Pragma("unroll") for (int rep = 0; rep < 8; rep++) { \
        int lin = rep * 256 + tid; int kk = lin >> 6, n = lin & 63; \
        CP4(su + ((bofs) + n * BPITCH + kk) * 4, \
            &(Bbase)[(long)((k0) + kk) * (ldb) + (c0) + n]); } }

// ---------------- adaLN fused dual GEMM (cp.async double-buffered) -----------
#define ADA_STRIDE (A_WORDS + 2 * B_WORDS)            // 9216 words
#define ADA_SMEM (2 * ADA_STRIDE * 4)                 // 73728 B
__global__ void __launch_bounds__(256, 2)
gemm_ada(const float* __restrict__ Wg_, const float* __restrict__ Wo_,
         const float* __restrict__ badag) {
    extern __shared__ float sm[];
    uint32_t su = smem_u32(sm);

    int tid = threadIdx.x, wid = tid >> 5;
    int g4 = (tid & 31) >> 2, q4 = tid & 3;
    int wr = (wid & 3) * 32, wc = (wid >> 2) * 32;
    int row0 = blockIdx.y * 128, col0 = blockIdx.x * 64;
    const float* A = g_sn;

    float acc1[2][4][4], acc2[2][4][4];
    ZERO_ACC(acc1); ZERO_ACC(acc2);

    ISSUEA(A, CS, 0, 0);
    ISSUEB(Wg_, CA, 0, col0, A_WORDS);
    ISSUEB(Wo_, CA, 0, col0, A_WORDS + B_WORDS);
    CP_COMMIT();
    const int KT = CS / 32;
    for (int kt = 0; kt < KT; kt++) {
        int cur = (kt & 1) * ADA_STRIDE;
        if (kt + 1 < KT) {
            int nxt = ((kt + 1) & 1) * ADA_STRIDE;
            int k0 = (kt + 1) * 32;
            ISSUEA(A, CS, k0, nxt);
            ISSUEB(Wg_, CA, k0, col0, nxt + A_WORDS);
            ISSUEB(Wo_, CA, k0, col0, nxt + A_WORDS + B_WORDS);
            CP_COMMIT();
            CP_WAIT1();
        } else { CP_WAIT0(); }
        __syncthreads();
        frag_compute2_cvt(sm + cur, sm + cur + A_WORDS, sm + cur + A_WORDS + B_WORDS,
                          acc1, acc2, wr, wc, g4, q4);
        __syncthreads();
    }

    float* st1 = sm;
    float* st2 = sm + STAGE_WORDS;
    stage_acc(st1, acc1, wr, wc, g4, q4);
    stage_acc(st2, acc2, wr, wc, g4, q4);
    __syncthreads();
    #pragma unroll
    for (int rep = 0; rep < 32; rep++) {
        int idx = rep * 256 + tid;
        int r = idx >> 6, c = idx & 63;
        int m = row0 + r, n = col0 + c;
        float v1 = st1[r * SPITCH + c], v2 = st2[r * SPITCH + c];
        g_an[(long)m * CA + n] = sigmoidf_(v1 + badag[n]) * g_lna[(long)m * CA + n] + v2;
    }
}

// ---------------- fused 4-way projection GEMM (cp.async, 4 CTAs/SM) ----------
#define GM_STRIDE (A_WORDS + B_WORDS)                 // 6912 words
#define PROJ_SMEM (2 * GM_STRIDE * 4)                 // 55296 B
__global__ void __launch_bounds__(256, 4)
gemm_proj4(const float* __restrict__ Wq, const float* __restrict__ Wk,
           const float* __restrict__ Wv, const float* __restrict__ Wg_,
           const float* __restrict__ bq) {
    extern __shared__ float sm[];
    uint32_t su = smem_u32(sm);

    int tid = threadIdx.x, wid = tid >> 5;
    int g4 = (tid & 31) >> 2, q4 = tid & 3;
    int wr = (wid & 3) * 32, wc = (wid >> 2) * 32;
    int row0 = blockIdx.y * 128;
    int cg = blockIdx.x * 64;
    int w = cg / CA, coln = cg % CA;
    const float* B = (w == 0) ? Wq : (w == 1) ? Wk : (w == 2) ? Wv : Wg_;
    const float* A = g_an;

    float acc[2][4][4];
    ZERO_ACC(acc);

    ISSUEA(A, CA, 0, 0);
    ISSUEB(B, CA, 0, coln, A_WORDS);
    CP_COMMIT();
    const int KT = CA / 32;
    for (int kt = 0; kt < KT; kt++) {
        int cur = (kt & 1) * GM_STRIDE;
        if (kt + 1 < KT) {
            int nxt = ((kt + 1) & 1) * GM_STRIDE;
            int k0 = (kt + 1) * 32;
            ISSUEA(A, CA, k0, nxt);
            ISSUEB(B, CA, k0, coln, nxt + A_WORDS);
            CP_COMMIT();
            CP_WAIT1();
        } else { CP_WAIT0(); }
        __syncthreads();
        frag_compute_cvt(sm + cur, sm + cur + A_WORDS, acc, wr, wc, g4, q4);
        __syncthreads();
    }

    float* st = sm;
    stage_acc(st, acc, wr, wc, g4, q4);
    __syncthreads();
    float* dst = (w == 0) ? g_q : (w == 1) ? g_k : g_v;
    #pragma unroll
    for (int rep = 0; rep < 32; rep++) {
        int idx = rep * 256 + tid;
        int r = idx >> 6, c = idx & 63;
        int m = row0 + r, n = coln + c;
        float v = st[r * SPITCH + c];
        if (w == 3) {
            g_gate[(long)m * CA + n] = v;
        } else {
            if (w == 0) v += bq[n];
            int b = m / SS, si = m % SS, h = n / HD, d = n % HD;
            dst[(((long)(b * HH + h) * SS) + si) * HD + d] = v;
        }
    }
}

// ---------------- fused output GEMM (cp.async double-buffered) ---------------
__global__ void __launch_bounds__(256, 2)
gemm_final(const float* __restrict__ Wout, const float* __restrict__ s_,
           const float* __restrict__ Wsg, const float* __restrict__ bsg,
           float* __restrict__ out) {
    extern __shared__ float sm[];
    uint32_t su = smem_u32(sm);

    int tid = threadIdx.x, wid = tid >> 5;
    int g4 = (tid & 31) >> 2, q4 = tid & 3;
    int wr = (wid & 3) * 32, wc = (wid >> 2) * 32;
    int row0 = blockIdx.y * 128, col0 = blockIdx.x * 64;

    float acc1[2][4][4], acc2[2][4][4];
    ZERO_ACC(acc1); ZERO_ACC(acc2);

    {
        const float* A = g_go;
        ISSUEA(A, CA, 0, 0);
        ISSUEB(Wout, CA, 0, col0, A_WORDS);
        CP_COMMIT();
        const int KT = CA / 32;
        for (int kt = 0; kt < KT; kt++) {
            int cur = (kt & 1) * GM_STRIDE;
            if (kt + 1 < KT) {
                int nxt = ((kt + 1) & 1) * GM_STRIDE;
                int k0 = (kt + 1) * 32;
                ISSUEA(A, CA, k0, nxt);
                ISSUEB(Wout, CA, k0, col0, nxt + A_WORDS);
                CP_COMMIT();
                CP_WAIT1();
            } else { CP_WAIT0(); }
            __syncthreads();
            frag_compute_cvt(sm + cur, sm + cur + A_WORDS, acc1, wr, wc, g4, q4);
            __syncthreads();
        }
    }
    {
        ISSUEA(s_, CS, 0, 0);
        ISSUEB(Wsg, CA, 0, col0, A_WORDS);
        CP_COMMIT();
        const int KT = CS / 32;
        for (int kt = 0; kt < KT; kt++) {
            int cur = (kt & 1) * GM_STRIDE;
            if (kt + 1 < KT) {
                int nxt = ((kt + 1) & 1) * GM_STRIDE;
                int k0 = (kt + 1) * 32;
                ISSUEA(s_, CS, k0, nxt);
                ISSUEB(Wsg, CA, k0, col0, nxt + A_WORDS);
                CP_COMMIT();
                CP_WAIT1();
            } else { CP_WAIT0(); }
            __syncthreads();
            frag_compute_cvt(sm + cur, sm + cur + A_WORDS, acc2, wr, wc, g4, q4);
            __syncthreads();
        }
    }

    #pragma unroll
    for (int mt = 0; mt < 2; mt++)
        #pragma unroll
        for (int nt = 0; nt < 4; nt++)
            #pragma unroll
            for (int t = 0; t < 4; t++) {
                int n = col0 + wc + nt * 8 + 2 * q4 + (t & 1);
                acc1[mt][nt][t] *= sigmoidf_(acc2[mt][nt][t] + __ldg(&bsg[n]));
            }

    float* st = sm;
    stage_acc(st, acc1, wr, wc, g4, q4);
    __syncthreads();
    #pragma unroll
    for (int rep = 0; rep < 32; rep++) {
        int idx = rep * 256 + tid;
        int r = idx >> 6, c = idx & 63;
        out[(long)(row0 + r) * CA + col0 + c] = st[r * SPITCH + c];
    }
}

// ---------------- pair bias v6: bf16 m16n8k16 MMA ----------------------------
#define WP 68
#define PB_Z_WORDS (64 * WP)                         // 4352
#define PB_WB_OFF  PB_Z_WORDS
#define PB_SMEM ((PB_Z_WORDS + 16 * WP) * 4)         // 21760 B
__global__ void __launch_bounds__(256)
pairbias6_kernel(const float* __restrict__ z, const float* __restrict__ beta,
                 const float* __restrict__ Wb, const float* __restrict__ gz,
                 const float* __restrict__ bz) {
    extern __shared__ float smf[];
    uint32_t* Z16  = (uint32_t*)smf;           // [64][WP] bf16x2
    uint32_t* Wb16 = Z16 + PB_WB_OFF;          // [16][WP] bf16x2
    float*    res  = smf;                      // aliased over Z16 after MMA
    __shared__ float gzs[CZ], bzs[CZ];

    int tid = threadIdx.x, wid = tid >> 5, lane = tid & 31;
    int g4 = lane >> 2, q4 = lane & 3;
    int b = blockIdx.z, p = blockIdx.y, q0 = blockIdx.x * 64;

    const float* zb = z + ((long)(b * SS + p) * SS + q0) * CZ;
    const float* betab = beta + ((long)(b * SS + p) * SS + q0) * HH;

    float betar[4];
    #pragma unroll
    for (int rep = 0; rep < 4; rep++)
        betar[rep] = betab[rep * 256 + tid];

    for (int idx = tid; idx < (CZ / 2) * HH; idx += 256) {
        int j = idx >> 4, h = idx & 15;
        Wb16[h * WP + j] = pack_bf16x2(Wb[(2 * j) * HH + h], Wb[(2 * j + 1) * HH + h]);
    }
    for (int idx = tid; idx < CZ; idx += 256) { gzs[idx] = gz[idx]; bzs[idx] = bz[idx]; }
    __syncthreads();

    {
        float4 vr[8];
        #pragma unroll
        for (int rr = 0; rr < 8; rr++) {
            int pl = wid * 8 + rr;
            vr[rr] = *(const float4*)&zb[(long)pl * CZ + lane * 4];
        }
        float sums[8], sqs[8];
        #pragma unroll
        for (int rr = 0; rr < 8; rr++) {
            float4 v = vr[rr];
            sums[rr] = v.x + v.y + v.z + v.w;
            sqs[rr]  = v.x * v.x + v.y * v.y + v.z * v.z + v.w * v.w;
        }
        #pragma unroll
        for (int o = 16; o; o >>= 1) {
            #pragma unroll
            for (int rr = 0; rr < 8; rr++) {
                sums[rr] += __shfl_xor_sync(0xffffffffu, sums[rr], o);
                sqs[rr]  += __shfl_xor_sync(0xffffffffu, sqs[rr],  o);
            }
        }
        #pragma unroll
        for (int rr = 0; rr < 8; rr++) {
            int pl = wid * 8 + rr;
            float mean = sums[rr] * (1.0f / CZ);
            float var  = sqs[rr] * (1.0f / CZ) - mean * mean;
            float rstd = rsqrtf(var + EPS);
            float4 v = vr[rr];
            int c = lane * 4;
            float z0 = (v.x - mean) * rstd * gzs[c + 0] + bzs[c + 0];
            float z1 = (v.y - mean) * rstd * gzs[c + 1] + bzs[c + 1];
            float z2 = (v.z - mean) * rstd * gzs[c + 2] + bzs[c + 2];
            float z3 = (v.w - mean) * rstd * gzs[c + 3] + bzs[c + 3];
            uint2 o2;
            o2.x = pack_bf16x2(z0, z1);
            o2.y = pack_bf16x2(z2, z3);
            *(uint2*)&Z16[pl * WP + lane * 2] = o2;
        }
    }
    __syncthreads();

    float acc[4];
    #pragma unroll
    for (int t = 0; t < 4; t++) acc[t] = 0.f;
    {
        int wr = (wid & 3) * 16;
        int hb = (wid >> 2) * 8;
        #pragma unroll
        for (int kc = 0; kc < 8; kc++) {
            int kb = kc * 8 + q4;
            uint32_t af[4];
            af[0] = Z16[(wr + g4) * WP + kb];
            af[1] = Z16[(wr + g4 + 8) * WP + kb];
            af[2] = Z16[(wr + g4) * WP + kb + 4];
            af[3] = Z16[(wr + g4 + 8) * WP + kb + 4];
            uint32_t bf[2];
            bf[0] = Wb16[(hb + g4) * WP + kb];
            bf[1] = Wb16[(hb + g4) * WP + kb + 4];
            mma_bf16(acc, af, bf);
        }
    }
    __syncthreads();

    {
        int wr = (wid & 3) * 16;
        int hb = (wid >> 2) * 8;
        #pragma unroll
        for (int t = 0; t < 4; t++) {
            int row = wr + g4 + ((t >= 2) ? 8 : 0);
            int h = hb + 2 * q4 + (t & 1);
            res[row * 17 + h] = acc[t];
        }
    }
    __syncthreads();

    #pragma unroll
    for (int rep = 0; rep < 4; rep++) {
        int idx = rep * 256 + tid;
        int ql = idx >> 4, hh = idx & 15;
        res[ql * 17 + hh] += betar[rep];
    }
    __syncthreads();

    #pragma unroll
    for (int rep = 0; rep < 4; rep++) {
        int idx = rep * 256 + tid;
        int h = idx >> 6, ql = idx & 63;
        g_bias[(((long)(b * HH + h) * SS) + p) * SS + q0 + ql] = res[ql * 17 + h];
    }
}

// ---------------- fused attention: pipelined K/V, direct-gmem bias -----------
#define QP 52
#define KP 52
#define VP 68
#define PP 68
#define AT_K (128 * QP)
#define AT_V (AT_K + 64 * KP)
#define AT_PB (AT_V + 48 * VP)
#define AT_WORDS (AT_PB + 128 * PP)
#define ATT_SMEM (AT_WORDS * 4)              // 87808 B

__global__ void __launch_bounds__(256, 2)
attn_kernel(const float* __restrict__ qg, const float* __restrict__ kg,
            const float* __restrict__ vg, const float* __restrict__ biasg,
            const float* __restrict__ gateg, float* __restrict__ outg) {
    extern __shared__ char smem[];
    uint32_t* Qs = (uint32_t*)smem;
    uint32_t* Ks = Qs + AT_K;
    uint32_t* Vs = Qs + AT_V;
    uint32_t* Ps = Qs + AT_PB;

    int tid = threadIdx.x, wid = tid >> 5, lane = tid & 31;
    int g4 = lane >> 2, q4 = lane & 3;
    int bh = blockIdx.y;
    int b = bh >> 4, h = bh & 15;
    int i0 = blockIdx.x * 128;
    const float* qb = qg + ((long)bh * SS + i0) * HD;
    const float* kb_ = kg + (long)bh * SS * HD;
    const float* vb = vg + (long)bh * SS * HD;
    const float* biasb = biasg + (long)bh * SS * SS;   // [j][i]

    #pragma unroll
    for (int rep = 0; rep < 6; rep++) {
        int idx = rep * 256 + tid;
        int r = idx / 12, c4 = (idx % 12) * 4;
        float4 v = *(const float4*)&qb[(long)r * HD + c4];
        uint32_t* d = &Qs[r * QP + c4];
        d[0] = f2tf32(v.x); d[1] = f2tf32(v.y); d[2] = f2tf32(v.z); d[3] = f2tf32(v.w);
    }

    int wr = wid * 16;
    float accO[6][4];
    #pragma unroll
    for (int n = 0; n < 6; n++)
        #pragma unroll
        for (int t = 0; t < 4; t++) accO[n][t] = 0.f;
    float mrow[2] = {-1e30f, -1e30f};
    float lrow[2] = {0.f, 0.f};

    float4 pk[3]; float pv[12];
    #pragma unroll
    for (int rep = 0; rep < 3; rep++) {
        int idx = rep * 256 + tid;
        int r = idx / 12, c4 = (idx % 12) * 4;
        pk[rep] = *(const float4*)&kb_[(long)r * HD + c4];
    }
    #pragma unroll
    for (int rep = 0; rep < 12; rep++) {
        int idx = rep * 256 + tid;
        int r = idx / 48, d = idx % 48;
        pv[rep] = vb[(long)r * HD + d];
    }

    for (int j = 0; j < 12; j++) {
        __syncthreads();
        #pragma unroll
        for (int rep = 0; rep < 3; rep++) {
            int idx = rep * 256 + tid;
            int r = idx / 12, c4 = (idx % 12) * 4;
            uint32_t* d = &Ks[r * KP + c4];
            d[0] = f2tf32(pk[rep].x); d[1] = f2tf32(pk[rep].y);
            d[2] = f2tf32(pk[rep].z); d[3] = f2tf32(pk[rep].w);
        }
        #pragma unroll
        for (int rep = 0; rep < 12; rep++) {
            int idx = rep * 256 + tid;
            int r = idx / 48, d = idx % 48;
            Vs[d * VP + r] = f2tf32(pv[rep]);
        }
        __syncthreads();
        if (j + 1 < 12) {
            #pragma unroll
            for (int rep = 0; rep < 3; rep++) {
                int idx = rep * 256 + tid;
                int r = idx / 12, c4 = (idx % 12) * 4;
                pk[rep] = *(const float4*)&kb_[(long)((j + 1) * 64 + r) * HD + c4];
            }
            #pragma unroll
            for (int rep = 0; rep < 12; rep++) {
                int idx = rep * 256 + tid;
                int r = idx / 48, d = idx % 48;
                pv[rep] = vb[(long)((j + 1) * 64 + r) * HD + d];
            }
        }

        float S[8][4];
        #pragma unroll
        for (int nt = 0; nt < 8; nt++)
            #pragma unroll
            for (int t = 0; t < 4; t++) S[nt][t] = 0.f;
        #pragma unroll
        for (int kc = 0; kc < 6; kc++) {
            int kbx = kc * 8 + q4;
            uint32_t af[4];
            af[0] = Qs[(wr + g4) * QP + kbx];
            af[1] = Qs[(wr + g4 + 8) * QP + kbx];
            af[2] = Qs[(wr + g4) * QP + kbx + 4];
            af[3] = Qs[(wr + g4 + 8) * QP + kbx + 4];
            #pragma unroll
            for (int nt = 0; nt < 8; nt++) {
                uint32_t bf2[2];
                bf2[0] = Ks[(nt * 8 + g4) * KP + kbx];
                bf2[1] = Ks[(nt * 8 + g4) * KP + kbx + 4];
                mma_tf32(S[nt], af, bf2);
            }
        }
        const float* bj = biasb + (long)(j * 64) * SS + i0;
        int r0 = wr + g4, r1 = r0 + 8;
        float mn0 = mrow[0], mn1 = mrow[1];
        #pragma unroll
        for (int nt = 0; nt < 8; nt++) {
            #pragma unroll
            for (int t = 0; t < 4; t++) {
                int rr = (t >= 2) ? r1 : r0;
                int cc = nt * 8 + 2 * q4 + (t & 1);
                float val = S[nt][t] * SCALE + __ldg(&bj[(long)cc * SS + rr]);
                S[nt][t] = val;
                if (t < 2) mn0 = fmaxf(mn0, val); else mn1 = fmaxf(mn1, val);
            }
        }
        mn0 = fmaxf(mn0, __shfl_xor_sync(0xffffffffu, mn0, 1));
        mn0 = fmaxf(mn0, __shfl_xor_sync(0xffffffffu, mn0, 2));
        mn1 = fmaxf(mn1, __shfl_xor_sync(0xffffffffu, mn1, 1));
        mn1 = fmaxf(mn1, __shfl_xor_sync(0xffffffffu, mn1, 2));
        float al0 = __expf(mrow[0] - mn0);
        float al1 = __expf(mrow[1] - mn1);
        mrow[0] = mn0; mrow[1] = mn1;
        float s0 = 0.f, s1 = 0.f;
        #pragma unroll
        for (int nt = 0; nt < 8; nt++) {
            #pragma unroll
            for (int t = 0; t < 4; t++) {
                float p = __expf(S[nt][t] - ((t >= 2) ? mn1 : mn0));
                S[nt][t] = p;
                if (t < 2) s0 += p; else s1 += p;
                int rr = (t >= 2) ? r1 : r0;
                int cc = nt * 8 + 2 * q4 + (t & 1);
                Ps[rr * PP + cc] = f2tf32(p);
            }
        }
        s0 += __shfl_xor_sync(0xffffffffu, s0, 1);
        s0 += __shfl_xor_sync(0xffffffffu, s0, 2);
        s1 += __shfl_xor_sync(0xffffffffu, s1, 1);
        s1 += __shfl_xor_sync(0xffffffffu, s1, 2);
        lrow[0] = lrow[0] * al0 + s0;
        lrow[1] = lrow[1] * al1 + s1;
        #pragma unroll
        for (int n = 0; n < 6; n++) {
            accO[n][0] *= al0; accO[n][1] *= al0;
            accO[n][2] *= al1; accO[n][3] *= al1;
        }
        __syncwarp();
        #pragma unroll
        for (int kc = 0; kc < 8; kc++) {
            int kbx = kc * 8 + q4;
            uint32_t af[4];
            af[0] = Ps[(wr + g4) * PP + kbx];
            af[1] = Ps[(wr + g4 + 8) * PP + kbx];
            af[2] = Ps[(wr + g4) * PP + kbx + 4];
            af[3] = Ps[(wr + g4 + 8) * PP + kbx + 4];
            #pragma unroll
            for (int n = 0; n < 6; n++) {
                uint32_t bf2[2];
                bf2[0] = Vs[(n * 8 + g4) * VP + kbx];
                bf2[1] = Vs[(n * 8 + g4) * VP + kbx + 4];
                mma_tf32(accO[n], af, bf2);
            }
        }
    }

    float inv0 = 1.0f / lrow[0], inv1 = 1.0f / lrow[1];
    #pragma unroll
    for (int n = 0; n < 6; n++) {
        #pragma unroll
        for (int t = 0; t < 4; t++) {
            int r = wr + g4 + ((t >= 2) ? 8 : 0);
            int c = n * 8 + 2 * q4 + (t & 1);
            long gi = ((long)(b * SS + i0 + r)) * CA + h * HD + c;
            float o = accO[n][t] * ((t >= 2) ? inv1 : inv0);
            outg[gi] = o * sigmoidf_(gateg[gi]);
        }
    }
}

// ---------------- host side --------------------------------------------------
static float* sym(const void* symbol) {
    void* p = nullptr;
    cudaGetSymbolAddress(&p, symbol);
    return (float*)p;
}

extern "C" void kernel_launch(void* const* d_in, const int* in_sizes, int n_in,
                              void* d_out, int out_size) {
    const float* a        = (const float*)d_in[0];
    const float* s        = (const float*)d_in[1];
    const float* z        = (const float*)d_in[2];
    const float* beta     = (const float*)d_in[3];
    const float* gamma_s  = (const float*)d_in[4];
    const float* W_ada_g  = (const float*)d_in[5];
    const float* b_ada_g  = (const float*)d_in[6];
    const float* W_ada_o  = (const float*)d_in[7];
    const float* Wq       = (const float*)d_in[8];
    const float* bq       = (const float*)d_in[9];
    const float* Wk       = (const float*)d_in[10];
    const float* Wv       = (const float*)d_in[11];
    const float* Wb       = (const float*)d_in[12];
    const float* gz       = (const float*)d_in[13];
    const float* bz       = (const float*)d_in[14];
    const float* Wg       = (const float*)d_in[15];
    const float* Wout     = (const float*)d_in[16];
    const float* Ws_gate  = (const float*)d_in[17];
    const float* bs_gate  = (const float*)d_in[18];
    float* out = (float*)d_out;

    float* p_q    = sym(g_q);
    float* p_k    = sym(g_k);
    float* p_v    = sym(g_v);
    float* p_gate = sym(g_gate);
    float* p_bias = sym(g_bias);
    float* p_go   = sym(g_go);

    cudaFuncSetAttribute(gemm_ada,        cudaFuncAttributeMaxDynamicSharedMemorySize, ADA_SMEM);
    cudaFuncSetAttribute(gemm_proj4,      cudaFuncAttributeMaxDynamicSharedMemorySize, PROJ_SMEM);
    cudaFuncSetAttribute(gemm_final,      cudaFuncAttributeMaxDynamicSharedMemorySize, PROJ_SMEM);
    cudaFuncSetAttribute(pairbias6_kernel,cudaFuncAttributeMaxDynamicSharedMemorySize, PB_SMEM);
    cudaFuncSetAttribute(attn_kernel,     cudaFuncAttributeMaxDynamicSharedMemorySize, ATT_SMEM);

    // serial schedule (R13) — multi-stream fork-join measured slower under
    // this harness's graph replay (R15: 591 vs 408), reverted.
    ln_kernel<<<MM, 256>>>(s, a, gamma_s);
    gemm_ada<<<dim3(CA / 64, MM / 128), 256, ADA_SMEM>>>(W_ada_g, W_ada_o, b_ada_g);
    gemm_proj4<<<dim3(4 * CA / 64, MM / 128), 256, PROJ_SMEM>>>(Wq, Wk, Wv, Wg, bq);
    pairbias6_kernel<<<dim3(SS / 64, SS, BB), 256, PB_SMEM>>>(z, beta, Wb, gz, bz);
    attn_kernel<<<dim3(SS / 128, BB * HH), 256, ATT_SMEM>>>(p_q, p_k, p_v, p_bias, p_gate, p_go);
    gemm_final<<<dim3(CA / 64, MM / 128), 256, PROJ_SMEM>>>(Wout, s, Ws_gate, bs_gate, out);
}